// round 7
// baseline (speedup 1.0000x reference)
#include <cuda_runtime.h>
#include <cuda_fp16.h>
#include <math.h>
#include <stdint.h>

#define T_ 1024
#define H_ 1024
#define I_ 1024
#define E_ 8
#define NP (T_*2)
#define HP (H_/2)      // 512 packed k-pairs per row
#define IP (I_/2)

#define BM 128
#define BN 64
#define BKP 16         // k-pairs per chunk (32 floats)
#define RS 20          // smem row stride (words) — conflict-free LDSM
#define MAXMT 16
#define NCH 32         // 512 kp / 16

// combine constants: D = (1 - 1/s)*C_HH + s*C_MM, s = 32
#define SC_C 0.96875f
#define SC_S 32.0f
#define SC_INV 0.03125f

// gemm1 stage layout (words): A 2x2560, B 4x1280
#define OFF_AH 0
#define OFF_AM 2560
#define OFF_GH 5120
#define OFF_GM 6400
#define OFF_UH 7680
#define OFF_UM 8960
#define STW1 10240
// gemm2: A 2x2560, B 2x1280
#define OFF_BH 5120
#define OFF_BM 6400
#define STW2 7680
#define SM1_BYTES ((128 + 3*STW1)*4)
#define SM2_BYTES ((128 + 3*STW2)*4)

// ---- routing scratch ----
__device__ float g_pair_w[NP];
__device__ int   g_offsets[E_+1];
__device__ int   g_perm[NP];

// ---- packed fp16 hi / scaled-residual, K-major (uint32 = half2 k-pair) ----
__device__ __align__(16) unsigned g_hidH[T_*HP],       g_hidM[T_*HP];        // [t][k]
__device__ __align__(16) unsigned g_w13H[E_*2*I_*HP],  g_w13M[E_*2*I_*HP];   // [e][f][k]
__device__ __align__(16) unsigned g_w2H [E_*H_*IP],    g_w2M [E_*H_*IP];     // [e][h][k]
__device__ __align__(16) unsigned g_actH[NP*IP],       g_actM[NP*IP];        // [p][k]

// ---------------------------------------------------------------------------
__device__ __forceinline__ void split_pack16(float x, float y, unsigned& h, unsigned& m) {
    __half2 hv = __floats2half2_rn(x, y);
    h = *(unsigned*)&hv;
    float hx = __low2float(hv), hy = __high2float(hv);
    __half2 mv = __floats2half2_rn(hx * SC_INV + (x - hx), hy * SC_INV + (y - hy));
    m = *(unsigned*)&mv;
}
__device__ __forceinline__ uint32_t smem_u32(const void* p) {
    uint32_t a;
    asm("{ .reg .u64 t; cvta.to.shared.u64 t, %1; cvt.u32.u64 %0, t; }" : "=r"(a) : "l"(p));
    return a;
}
#define CP16(dst, src, sz) \
    asm volatile("cp.async.cg.shared.global [%0], [%1], 16, %2;" :: "r"(dst), "l"(src), "r"(sz) : "memory")
#define CP_COMMIT() asm volatile("cp.async.commit_group;" ::: "memory")
#define CP_WAIT0()  asm volatile("cp.async.wait_group 0;" ::: "memory")
#define CP_WAIT1()  asm volatile("cp.async.wait_group 1;" ::: "memory")

#define MMA(c, a, b0_, b1_)                                                   \
    asm volatile("mma.sync.aligned.m16n8k16.row.col.f32.f16.f16.f32 "         \
        "{%0,%1,%2,%3}, {%4,%5,%6,%7}, {%8,%9}, {%0,%1,%2,%3};"               \
        : "+f"((c)[0]), "+f"((c)[1]), "+f"((c)[2]), "+f"((c)[3])              \
        : "r"((a)[0]), "r"((a)[1]), "r"((a)[2]), "r"((a)[3]),                 \
          "r"(b0_), "r"(b1_))

#define LDSM4(r, a)                                                           \
    asm volatile("ldmatrix.sync.aligned.m8n8.x4.shared.b16 {%0,%1,%2,%3}, [%4];" \
        : "=r"((r)[0]), "=r"((r)[1]), "=r"((r)[2]), "=r"((r)[3]) : "r"(a))

// ---------------------------------------------------------------------------
// pack hidden (also zeroes out — same index space)
// ---------------------------------------------------------------------------
__global__ void k_pack_hid(const float* __restrict__ hid, float* __restrict__ out) {
    int i = blockIdx.x * 256 + threadIdx.x;           // T*HP/4 units
    const float4* s = (const float4*)hid + (size_t)i * 2;
    float4 a = s[0], b = s[1];
    uint4 Hh, Mm;
    split_pack16(a.x, a.y, Hh.x, Mm.x);
    split_pack16(a.z, a.w, Hh.y, Mm.y);
    split_pack16(b.x, b.y, Hh.z, Mm.z);
    split_pack16(b.z, b.w, Hh.w, Mm.w);
    ((uint4*)g_hidH)[i] = Hh;
    ((uint4*)g_hidM)[i] = Mm;
    float4 z = make_float4(0.f, 0.f, 0.f, 0.f);
    ((float4*)out)[2 * i]     = z;
    ((float4*)out)[2 * i + 1] = z;
}

__global__ void k_route(const float* __restrict__ logits) {
    __shared__ int cnt[E_], cur[E_], soff[E_ + 1];
    int t = threadIdx.x;
    if (t < E_) { cnt[t] = 0; cur[t] = 0; }
    __syncthreads();
    float l[E_];
#pragma unroll
    for (int e = 0; e < E_; e++) l[e] = logits[t * E_ + e];
    int i0 = 0;
#pragma unroll
    for (int e = 1; e < E_; e++) if (l[e] > l[i0]) i0 = e;
    int i1 = -1;
#pragma unroll
    for (int e = 0; e < E_; e++)
        if (e != i0 && (i1 < 0 || l[e] > l[i1])) i1 = e;
    g_pair_w[2 * t]     = 1.f / (1.f + expf(l[i1] - l[i0]));
    g_pair_w[2 * t + 1] = 1.f / (1.f + expf(l[i0] - l[i1]));
    atomicAdd(&cnt[i0], 1);
    atomicAdd(&cnt[i1], 1);
    __syncthreads();
    if (t == 0) {
        int o = 0;
        for (int e = 0; e < E_; e++) { soff[e] = o; o += cnt[e]; }
        soff[E_] = o;
    }
    __syncthreads();
    if (t <= E_) g_offsets[t] = soff[t];
    int p0 = atomicAdd(&cur[i0], 1);
    g_perm[soff[i0] + p0] = 2 * t;
    int p1 = atomicAdd(&cur[i1], 1);
    g_perm[soff[i1] + p1] = 2 * t + 1;
}

// W13 [e][h][f] -> K-major [e][f][h/2] hi/res, 64x64 smem transpose
__global__ __launch_bounds__(256) void k_pack_w13T(const float* __restrict__ W) {
    __shared__ float s[64][65];
    int e = blockIdx.z, h0 = blockIdx.y * 64, f0 = blockIdx.x * 64;
    const float* src = W + ((size_t)e * H_ + h0) * (2 * I_) + f0;
    int tid = threadIdx.x;
#pragma unroll
    for (int i = 0; i < 4; i++) {
        int r = (tid >> 4) + i * 16, c = (tid & 15) * 4;
        float4 v = *(const float4*)&src[(size_t)r * (2 * I_) + c];
        s[r][c] = v.x; s[r][c+1] = v.y; s[r][c+2] = v.z; s[r][c+3] = v.w;
    }
    __syncthreads();
    int fr = tid >> 2, hp0 = (tid & 3) * 8;
    unsigned hb[8], mb[8];
#pragma unroll
    for (int j = 0; j < 8; j++)
        split_pack16(s[2*(hp0+j)][fr], s[2*(hp0+j)+1][fr], hb[j], mb[j]);
    size_t d = ((size_t)e * (2*I_) + f0 + fr) * HP + (h0 >> 1) + hp0;
    *(uint4*)&g_w13H[d] = *(uint4*)&hb[0]; *(uint4*)&g_w13H[d+4] = *(uint4*)&hb[4];
    *(uint4*)&g_w13M[d] = *(uint4*)&mb[0]; *(uint4*)&g_w13M[d+4] = *(uint4*)&mb[4];
}

// W2 [e][i][h] -> K-major [e][h][i/2]
__global__ __launch_bounds__(256) void k_pack_w2T(const float* __restrict__ W) {
    __shared__ float s[64][65];
    int e = blockIdx.z, i0 = blockIdx.y * 64, h0 = blockIdx.x * 64;
    const float* src = W + ((size_t)e * I_ + i0) * H_ + h0;
    int tid = threadIdx.x;
#pragma unroll
    for (int i = 0; i < 4; i++) {
        int r = (tid >> 4) + i * 16, c = (tid & 15) * 4;
        float4 v = *(const float4*)&src[(size_t)r * H_ + c];
        s[r][c] = v.x; s[r][c+1] = v.y; s[r][c+2] = v.z; s[r][c+3] = v.w;
    }
    __syncthreads();
    int hr = tid >> 2, ip0 = (tid & 3) * 8;
    unsigned hb[8], mb[8];
#pragma unroll
    for (int j = 0; j < 8; j++)
        split_pack16(s[2*(ip0+j)][hr], s[2*(ip0+j)+1][hr], hb[j], mb[j]);
    size_t d = ((size_t)e * H_ + h0 + hr) * IP + (i0 >> 1) + ip0;
    *(uint4*)&g_w2H[d] = *(uint4*)&hb[0]; *(uint4*)&g_w2H[d+4] = *(uint4*)&hb[4];
    *(uint4*)&g_w2M[d] = *(uint4*)&mb[0]; *(uint4*)&g_w2M[d+4] = *(uint4*)&mb[4];
}

// ---------------------------------------------------------------------------
// GEMM1: act = silu(X@Wg)*(X@Wu). ldmatrix frags, depth-3 cp.async ring.
// ---------------------------------------------------------------------------
__global__ __launch_bounds__(256, 1) void k_gemm1() {
    extern __shared__ __align__(16) unsigned smem[];
    uint32_t sb = smem_u32(smem);
    int* s_pair = (int*)smem;                 // [128]

    int e  = blockIdx.y >> 4;
    int mt = blockIdx.y & 15;
    int off = g_offsets[e], cnt = g_offsets[e + 1] - off;
    if (mt * BM >= cnt) return;

    int tid = threadIdx.x;
    if (tid < BM) {
        int r = mt * BM + tid;
        s_pair[tid] = (r < cnt) ? g_perm[off + r] : -1;
    }
    __syncthreads();

    int n0 = blockIdx.x * BN;
    int wid = tid >> 5, lane = tid & 31;
    int wm = wid >> 2, wn = wid & 3;          // 2 x 4 warps
    int g = lane >> 2, tg = lane & 3;

    // LDSM lane offset (bytes, within a tile)
    int arow = (lane & 7) + ((lane >> 3) & 1) * 8;
    uint32_t loff = (uint32_t)(arow * RS + (lane >> 4) * 4) * 4;

    // staging roles
    int ar = tid >> 2, aseg = (tid & 3) * 4;  // words

    float cgH[4][2][4] = {}, cgM[4][2][4] = {};
    float cuH[4][2][4] = {}, cuM[4][2][4] = {};

    auto stage = [&](int c) {
        uint32_t s0 = sb + (128 + (c % 3) * STW1) * 4;
        int kof = c * BKP;
#pragma unroll
        for (int j = 0; j < 2; j++) {
            int m = ar + j * 64;
            int p = s_pair[m];
            uint32_t sz = (p >= 0) ? 16u : 0u;
            size_t so = (p >= 0) ? ((size_t)(p >> 1) * HP + kof + aseg) : 0;
            uint32_t ad = s0 + (m * RS + aseg) * 4;
            CP16(ad + OFF_AH * 4, g_hidH + so, sz);
            CP16(ad + OFF_AM * 4, g_hidM + so, sz);
        }
        size_t gf = ((size_t)e * (2 * I_) + n0 + ar) * HP + kof + aseg;
        size_t uf = gf + (size_t)I_ * HP;
        uint32_t bd = s0 + (ar * RS + aseg) * 4;
        CP16(bd + OFF_GH * 4, g_w13H + gf, 16);
        CP16(bd + OFF_GM * 4, g_w13M + gf, 16);
        CP16(bd + OFF_UH * 4, g_w13H + uf, 16);
        CP16(bd + OFF_UM * 4, g_w13M + uf, 16);
        CP_COMMIT();
    };

    stage(0); stage(1);
    for (int c = 0; c < NCH; c++) {
        if (c + 1 < NCH) { CP_WAIT1(); } else { CP_WAIT0(); }
        __syncthreads();
        if (c + 2 < NCH) stage(c + 2);
        uint32_t st = sb + (128 + (c % 3) * STW1) * 4;
#pragma unroll
        for (int ks = 0; ks < 2; ks++) {
            uint32_t kb = (uint32_t)(ks * 8) * 4;
            uint32_t bbase = st + (uint32_t)(wn * 16 * RS) * 4 + kb + loff;
            unsigned gh[4], gm[4], uh[4], um[4];
            LDSM4(gh, bbase + OFF_GH * 4);
            LDSM4(gm, bbase + OFF_GM * 4);
            LDSM4(uh, bbase + OFF_UH * 4);
            LDSM4(um, bbase + OFF_UM * 4);
#pragma unroll
            for (int mf = 0; mf < 4; mf++) {
                uint32_t abase = st + (uint32_t)((wm * 64 + mf * 16) * RS) * 4 + kb + loff;
                unsigned ah[4], am[4];
                LDSM4(ah, abase + OFF_AH * 4);
                LDSM4(am, abase + OFF_AM * 4);
                MMA(cgH[mf][0], ah, gh[0], gh[2]);
                MMA(cgH[mf][1], ah, gh[1], gh[3]);
                MMA(cgM[mf][0], am, gm[0], gm[2]);
                MMA(cgM[mf][1], am, gm[1], gm[3]);
                MMA(cuH[mf][0], ah, uh[0], uh[2]);
                MMA(cuH[mf][1], ah, uh[1], uh[3]);
                MMA(cuM[mf][0], am, um[0], um[2]);
                MMA(cuM[mf][1], am, um[1], um[3]);
            }
        }
    }

    // epilogue: combine, silu(gate)*up -> packed fp16 H/M act (K-major)
    int pcb = (n0 >> 1) + wn * 8;
#pragma unroll
    for (int mf = 0; mf < 4; mf++) {
#pragma unroll
        for (int half = 0; half < 2; half++) {
            int p = s_pair[wm * 64 + mf * 16 + g + half * 8];
            if (p < 0) continue;
            size_t rowo = (size_t)p * IP;
#pragma unroll
            for (int nf = 0; nf < 2; nf++) {
                float g0 = SC_C * cgH[mf][nf][half*2+0] + SC_S * cgM[mf][nf][half*2+0];
                float g1 = SC_C * cgH[mf][nf][half*2+1] + SC_S * cgM[mf][nf][half*2+1];
                float u0 = SC_C * cuH[mf][nf][half*2+0] + SC_S * cuM[mf][nf][half*2+0];
                float u1 = SC_C * cuH[mf][nf][half*2+1] + SC_S * cuM[mf][nf][half*2+1];
                float a0 = u0 * g0 / (1.f + expf(-g0));
                float a1 = u1 * g1 / (1.f + expf(-g1));
                unsigned hh, mm;
                split_pack16(a0, a1, hh, mm);
                int cidx = pcb + nf * 4 + tg;
                g_actH[rowo + cidx] = hh;
                g_actM[rowo + cidx] = mm;
            }
        }
    }
}

// ---------------------------------------------------------------------------
// GEMM2: out[t] += w_p * (act[p] @ W2[e]); ldmatrix, depth-3 ring
// ---------------------------------------------------------------------------
__global__ __launch_bounds__(256, 2) void k_gemm2(float* __restrict__ out) {
    extern __shared__ __align__(16) unsigned smem[];
    uint32_t sb = smem_u32(smem);
    int* s_pair = (int*)smem;

    int e  = blockIdx.y >> 4;
    int mt = blockIdx.y & 15;
    int off = g_offsets[e], cnt = g_offsets[e + 1] - off;
    if (mt * BM >= cnt) return;

    int tid = threadIdx.x;
    if (tid < BM) {
        int r = mt * BM + tid;
        s_pair[tid] = (r < cnt) ? g_perm[off + r] : -1;
    }
    __syncthreads();

    int n0 = blockIdx.x * BN;
    int wid = tid >> 5, lane = tid & 31;
    int wm = wid >> 2, wn = wid & 3;
    int g = lane >> 2, tg = lane & 3;

    int arow = (lane & 7) + ((lane >> 3) & 1) * 8;
    uint32_t loff = (uint32_t)(arow * RS + (lane >> 4) * 4) * 4;

    int ar = tid >> 2, aseg = (tid & 3) * 4;

    float ccH[4][2][4] = {}, ccM[4][2][4] = {};

    auto stage = [&](int c) {
        uint32_t s0 = sb + (128 + (c % 3) * STW2) * 4;
        int kof = c * BKP;
#pragma unroll
        for (int j = 0; j < 2; j++) {
            int m = ar + j * 64;
            int p = s_pair[m];
            uint32_t sz = (p >= 0) ? 16u : 0u;
            size_t so = (p >= 0) ? ((size_t)p * IP + kof + aseg) : 0;
            uint32_t ad = s0 + (m * RS + aseg) * 4;
            CP16(ad + OFF_AH * 4, g_actH + so, sz);
            CP16(ad + OFF_AM * 4, g_actM + so, sz);
        }
        size_t bf = ((size_t)e * H_ + n0 + ar) * IP + kof + aseg;
        uint32_t bd = s0 + (ar * RS + aseg) * 4;
        CP16(bd + OFF_BH * 4, g_w2H + bf, 16);
        CP16(bd + OFF_BM * 4, g_w2M + bf, 16);
        CP_COMMIT();
    };

    stage(0); stage(1);
    for (int c = 0; c < NCH; c++) {
        if (c + 1 < NCH) { CP_WAIT1(); } else { CP_WAIT0(); }
        __syncthreads();
        if (c + 2 < NCH) stage(c + 2);
        uint32_t st = sb + (128 + (c % 3) * STW2) * 4;
#pragma unroll
        for (int ks = 0; ks < 2; ks++) {
            uint32_t kb = (uint32_t)(ks * 8) * 4;
            uint32_t bbase = st + (uint32_t)(wn * 16 * RS) * 4 + kb + loff;
            unsigned bh[4], bm[4];
            LDSM4(bh, bbase + OFF_BH * 4);
            LDSM4(bm, bbase + OFF_BM * 4);
#pragma unroll
            for (int mf = 0; mf < 4; mf++) {
                uint32_t abase = st + (uint32_t)((wm * 64 + mf * 16) * RS) * 4 + kb + loff;
                unsigned ah[4], am[4];
                LDSM4(ah, abase + OFF_AH * 4);
                LDSM4(am, abase + OFF_AM * 4);
                MMA(ccH[mf][0], ah, bh[0], bh[2]);
                MMA(ccH[mf][1], ah, bh[1], bh[3]);
                MMA(ccM[mf][0], am, bm[0], bm[2]);
                MMA(ccM[mf][1], am, bm[1], bm[3]);
            }
        }
    }

#pragma unroll
    for (int mf = 0; mf < 4; mf++) {
#pragma unroll
        for (int half = 0; half < 2; half++) {
            int p = s_pair[wm * 64 + mf * 16 + g + half * 8];
            if (p < 0) continue;
            int   t = p >> 1;
            float w = g_pair_w[p];
            float* dst = out + (size_t)t * H_ + n0 + wn * 16 + 2 * tg;
#pragma unroll
            for (int nf = 0; nf < 2; nf++) {
                float r0 = SC_C * ccH[mf][nf][half*2+0] + SC_S * ccM[mf][nf][half*2+0];
                float r1 = SC_C * ccH[mf][nf][half*2+1] + SC_S * ccM[mf][nf][half*2+1];
                atomicAdd(&dst[nf * 8],     w * r0);
                atomicAdd(&dst[nf * 8 + 1], w * r1);
            }
        }
    }
}

// ---------------------------------------------------------------------------
extern "C" void kernel_launch(void* const* d_in, const int* in_sizes, int n_in,
                              void* d_out, int out_size) {
    const float* hid    = (const float*)d_in[0];   // [T, H]
    const float* logits = (const float*)d_in[1];   // [T, E]
    const float* W13    = (const float*)d_in[2];   // [E, H, 2I]
    const float* W2     = (const float*)d_in[3];   // [E, I, H]
    float* out = (float*)d_out;                    // [T, H]

    cudaFuncSetAttribute(k_gemm1, cudaFuncAttributeMaxDynamicSharedMemorySize, SM1_BYTES);
    cudaFuncSetAttribute(k_gemm2, cudaFuncAttributeMaxDynamicSharedMemorySize, SM2_BYTES);

    k_pack_hid<<<(T_ * HP / 4) / 256, 256>>>(hid, out);
    k_route<<<1, 1024>>>(logits);
    k_pack_w13T<<<dim3(2 * I_ / 64, H_ / 64, E_), 256>>>(W13);
    k_pack_w2T<<<dim3(H_ / 64, I_ / 64, E_), 256>>>(W2);

    dim3 g1(I_ / BN, E_ * MAXMT);
    k_gemm1<<<g1, 256, SM1_BYTES>>>();
    dim3 g2(H_ / BN, E_ * MAXMT);
    k_gemm2<<<g2, 256, SM2_BYTES>>>(out);
}